// round 13
// baseline (speedup 1.0000x reference)
#include <cuda_runtime.h>
#include <cuda_fp16.h>
#include <cstdint>

// ---------------- problem constants ----------------
static constexpr int MDIM = 4096;   // batch
static constexpr int NDIM = 4096;   // out features
static constexpr int KDIM = 4096;   // in features

static constexpr int BM = 128;
static constexpr int BN = 128;
static constexpr int BK = 64;                // halves per stage (128B rows)
static constexpr int THREADS = 256;          // 8 warps: 4 (m) x 2 (n), warp tile 32x64

static constexpr int TILES      = (MDIM / BM) * (NDIM / BN);  // 1024
static constexpr int FULL_TILES = 888;       // exactly 3 waves of 296 (2 CTAs x 148 SMs)
static constexpr int TAIL_TILES = TILES - FULL_TILES;         // 136 -> 272 split CTAs

static constexpr uint32_t ASTAGE = BM * BK * 2;            // 16 KB
static constexpr uint32_t BSTAGE = BN * BK * 2;            // 16 KB
static constexpr uint32_t SLOT   = ASTAGE + BSTAGE;        // 32 KB
static constexpr uint32_t SMEM_TOTAL = 3 * SLOT;           // 96 KB -> 2 CTAs/SM

// ---------------- scratch (device globals: allocations are banned) ----------------
__device__ __align__(1024) __half g_wm[(size_t)NDIM * KDIM];  // fp16 masked weight
__device__ __align__(1024) __half g_xr[(size_t)MDIM * KDIM];  // fp16 x

// ---------------- sm_80-safe PTX helpers ----------------
__device__ __forceinline__ uint32_t smem_u32(const void* p) {
    uint32_t a;
    asm("{ .reg .u64 t; cvta.to.shared.u64 t, %1; cvt.u32.u64 %0, t; }" : "=r"(a) : "l"(p));
    return a;
}
__device__ __forceinline__ void cp_async16(uint32_t dst, const void* src) {
    asm volatile("cp.async.cg.shared.global [%0], [%1], 16;" :: "r"(dst), "l"(src) : "memory");
}
__device__ __forceinline__ void cp_commit() {
    asm volatile("cp.async.commit_group;" ::: "memory");
}
template <int N>
__device__ __forceinline__ void cp_wait() {
    asm volatile("cp.async.wait_group %0;" :: "n"(N) : "memory");
}
// Named-barrier producer/consumer split: 256 arrives + 256 syncs = 512.
__device__ __forceinline__ void bar_arrive_1() {
    asm volatile("bar.arrive 1, 512;" ::: "memory");
}
__device__ __forceinline__ void bar_sync_1() {
    asm volatile("bar.sync 1, 512;" ::: "memory");
}
__device__ __forceinline__ void ldsm_x4(uint32_t* r, uint32_t addr) {
    asm volatile("ldmatrix.sync.aligned.m8n8.x4.shared.b16 {%0,%1,%2,%3}, [%4];"
                 : "=r"(r[0]), "=r"(r[1]), "=r"(r[2]), "=r"(r[3]) : "r"(addr));
}
__device__ __forceinline__ void mma_f16(float* c, const uint32_t* a, const uint32_t* b) {
    asm volatile(
        "mma.sync.aligned.m16n8k16.row.col.f32.f16.f16.f32 "
        "{%0,%1,%2,%3}, {%4,%5,%6,%7}, {%8,%9}, {%0,%1,%2,%3};"
        : "+f"(c[0]), "+f"(c[1]), "+f"(c[2]), "+f"(c[3])
        : "r"(a[0]), "r"(a[1]), "r"(a[2]), "r"(a[3]), "r"(b[0]), "r"(b[1]));
}

// ---------------- prep: masked weight + x, both converted to fp16 RN ----------------
__global__ void prep_kernel(const float4* __restrict__ w, const float4* __restrict__ msk,
                            const float4* __restrict__ x, uint2* __restrict__ wm,
                            uint2* __restrict__ xr, int n4) {
    int stride = gridDim.x * blockDim.x;
    for (int i = blockIdx.x * blockDim.x + threadIdx.x; i < n4; i += stride) {
        float4 a = w[i], b = msk[i];
        __half2 lo = __floats2half2_rn(a.x * b.x, a.y * b.y);
        __half2 hi = __floats2half2_rn(a.z * b.z, a.w * b.w);
        uint2 o;
        o.x = *reinterpret_cast<uint32_t*>(&lo);
        o.y = *reinterpret_cast<uint32_t*>(&hi);
        wm[i] = o;
        float4 c = x[i];
        __half2 l2 = __floats2half2_rn(c.x, c.y);
        __half2 h2 = __floats2half2_rn(c.z, c.w);
        uint2 p;
        p.x = *reinterpret_cast<uint32_t*>(&l2);
        p.y = *reinterpret_cast<uint32_t*>(&h2);
        xr[i] = p;
    }
}

// ---------------- zero the tail-tile region of out (atomic accumulation base) ----------
__global__ void zero_tail_kernel(float* __restrict__ out) {
    int t  = FULL_TILES + blockIdx.x;           // tile id 888..1023
    int m0 = (t & 31) * BM;
    int n0 = (t >> 5) * BN;
    // 128 rows x 128 cols = 4096 float4; 256 threads x 16 each
    #pragma unroll
    for (int i = 0; i < 16; i++) {
        int id = threadIdx.x + 256 * i;
        int r = id >> 5, c = (id & 31) * 4;
        *reinterpret_cast<float4*>(out + (size_t)(m0 + r) * NDIM + n0 + c) =
            make_float4(0.f, 0.f, 0.f, 0.f);
    }
}

// ---------------- fp16 mma.sync GEMM: y = Xh * Wmh^T + bias (fp32 accum) ----------------
// Verified R12 body, templated:
//   KIT   = K iterations this CTA performs (64 full-K, 32 for split-K tiles)
//   SPLIT = tail path: tile id = FULL_TILES + bx/2, kz = bx&1; epilogue atomicAdd
//           into the pre-zeroed region (bias contributed by kz==0 only).
// Exactly two float contributions land on each split output; float add of two
// values commutes bit-exactly over a 0.0 base, so the result is deterministic.
template <int KIT, bool SPLIT>
__global__ void __launch_bounds__(THREADS, 2)
gemm_kernel(const __half* __restrict__ A,   // g_xr [M][K] fp16
            const __half* __restrict__ B,   // g_wm [N][K] fp16
            const float* __restrict__ bias,
            float* __restrict__ out) {
    extern __shared__ char smem[];
    const uint32_t sbase = smem_u32(smem);
    const int tid  = threadIdx.x;
    const int lane = tid & 31;
    const int wid  = tid >> 5;
    const int wm   = wid & 3;   // warp m position (x32): 4
    const int wn   = wid >> 2;  // warp n position (x64): 2

    int tile, kz;
    if (SPLIT) {
        tile = FULL_TILES + ((int)blockIdx.x >> 1);
        kz   = (int)blockIdx.x & 1;
    } else {
        tile = (int)blockIdx.x;
        kz   = 0;
    }
    const int m0 = (tile & 31) * BM;   // m fastest -> x panels stay L2-hot
    const int n0 = (tile >> 5) * BN;
    const __half* gA = A + (size_t)m0 * KDIM + kz * (KIT * BK);
    const __half* gB = B + (size_t)n0 * KDIM + kz * (KIT * BK);

    // -------- stage loader: 8 x 16B cp.async per thread --------
    auto load_stage = [&](int kt, uint32_t st) {
        const int kof = kt * BK;
        #pragma unroll
        for (int i = 0; i < 4; i++) {                 // A: 1024 chunks (128 rows x 8)
            int id = tid + THREADS * i;
            int r = id >> 3, c = id & 7;
            cp_async16(st + r * 128 + ((c ^ (r & 7)) << 4),
                       gA + (size_t)r * KDIM + kof + c * 8);
        }
        #pragma unroll
        for (int i = 0; i < 4; i++) {                 // B: 1024 chunks
            int id = tid + THREADS * i;
            int r = id >> 3, c = id & 7;
            cp_async16(st + ASTAGE + r * 128 + ((c ^ (r & 7)) << 4),
                       gB + (size_t)r * KDIM + kof + c * 8);
        }
    };

    // -------- per-lane fragment base addresses (relative to stage base) --------
    uint32_t afB[2], bfB[4];
    #pragma unroll
    for (int mt = 0; mt < 2; mt++) {
        int r = wm * 32 + mt * 16 + (lane & 15);
        int b = lane >> 4, k = r & 7;
        afB[mt] = r * 128 + (((b ^ (k & 1)) | (k & 6)) << 4);
    }
    #pragma unroll
    for (int p = 0; p < 4; p++) {
        int r = wn * 64 + p * 16 + (lane & 7) + ((lane >> 4) << 3);
        int b = (lane >> 3) & 1, k = r & 7;
        bfB[p] = (ASTAGE + r * 128) + (((b ^ (k & 1)) | (k & 6)) << 4);
    }

    float acc[2][8][4];
    #pragma unroll
    for (int mt = 0; mt < 2; mt++)
        #pragma unroll
        for (int nt = 0; nt < 8; nt++)
            #pragma unroll
            for (int i = 0; i < 4; i++) acc[mt][nt][i] = 0.0f;

    // -------- prologue: stages 0,1 in flight --------
    uint32_t stC = sbase, stN = sbase + SLOT, stL = sbase + 2 * SLOT;
    load_stage(0, stC); cp_commit();
    load_stage(1, stN); cp_commit();
    cp_wait<1>();
    __syncthreads();

    // -------- main K loop --------
    for (int kt = 0; kt < KIT; kt++) {
        if (kt) bar_sync_1();   // all kt-1 arrives seen: stL free, stage-kt data published
        if (kt + 2 < KIT) load_stage(kt + 2, stL);
        cp_commit();  // always commit to keep group accounting uniform

        #pragma unroll
        for (int s = 0; s < 3; s++) {                 // k16 steps 0..2
            const uint32_t sx = (uint32_t)(s << 5);
            uint32_t af[2][4], bf[8][2];
            #pragma unroll
            for (int mt = 0; mt < 2; mt++)
                ldsm_x4(af[mt], stC + (afB[mt] ^ sx));
            #pragma unroll
            for (int p = 0; p < 4; p++) {
                uint32_t t[4];
                ldsm_x4(t, stC + (bfB[p] ^ sx));
                bf[2 * p][0] = t[0];     bf[2 * p][1] = t[1];
                bf[2 * p + 1][0] = t[2]; bf[2 * p + 1][1] = t[3];
            }
            #pragma unroll
            for (int mt = 0; mt < 2; mt++)
                #pragma unroll
                for (int nt = 0; nt < 8; nt++)
                    mma_f16(acc[mt][nt], af[mt], bf[nt]);
        }

        // ----- step s=3: LDSM, publish (non-blocking), then register-only MMAs -----
        {
            const uint32_t sx = 3u << 5;
            uint32_t af[2][4], bf[8][2];
            #pragma unroll
            for (int mt = 0; mt < 2; mt++)
                ldsm_x4(af[mt], stC + (afB[mt] ^ sx));
            #pragma unroll
            for (int p = 0; p < 4; p++) {
                uint32_t t[4];
                ldsm_x4(t, stC + (bfB[p] ^ sx));
                bf[2 * p][0] = t[0];     bf[2 * p][1] = t[1];
                bf[2 * p + 1][0] = t[2]; bf[2 * p + 1][1] = t[3];
            }
            cp_wait<1>();      // my stage-(kt+1) cp.async group complete
            bar_arrive_1();    // non-blocking: reads of stC done + data landed
            #pragma unroll
            for (int mt = 0; mt < 2; mt++)
                #pragma unroll
                for (int nt = 0; nt < 8; nt++)
                    mma_f16(acc[mt][nt], af[mt], bf[nt]);
        }

        uint32_t t = stC; stC = stN; stN = stL; stL = t;
    }
    cp_wait<0>();  // drain tail groups before exit

    // -------- epilogue --------
    const int r  = lane >> 2;
    const int c2 = (lane & 3) * 2;
    const float* bp = bias + n0 + wn * 64;
    float* op = out + (size_t)(m0 + wm * 32) * NDIM + n0 + wn * 64;

    #pragma unroll
    for (int mt = 0; mt < 2; mt++) {
        #pragma unroll
        for (int nt = 0; nt < 8; nt++) {
            int n = nt * 8 + c2;
            float b0, b1;
            if (SPLIT) {
                b0 = (kz == 0) ? __ldg(bp + n) : 0.0f;      // bias once (kz=0 half)
                b1 = (kz == 0) ? __ldg(bp + n + 1) : 0.0f;
            } else {
                b0 = __ldg(bp + n); b1 = __ldg(bp + n + 1);
            }
            float v00 = acc[mt][nt][0] + b0, v01 = acc[mt][nt][1] + b1;
            float v10 = acc[mt][nt][2] + b0, v11 = acc[mt][nt][3] + b1;
            float* p0 = op + (size_t)(mt * 16 + r) * NDIM + n;
            float* p1 = op + (size_t)(mt * 16 + r + 8) * NDIM + n;
            if (SPLIT) {
                atomicAdd(p0, v00); atomicAdd(p0 + 1, v01);
                atomicAdd(p1, v10); atomicAdd(p1 + 1, v11);
            } else {
                *reinterpret_cast<float2*>(p0) = make_float2(v00, v01);
                *reinterpret_cast<float2*>(p1) = make_float2(v10, v11);
            }
        }
    }
}

// ---------------- host ----------------
extern "C" void kernel_launch(void* const* d_in, const int* in_sizes, int n_in,
                              void* d_out, int out_size) {
    const float* x    = (const float*)d_in[0];
    const float* w    = (const float*)d_in[1];
    const float* bias = (const float*)d_in[2];
    const float* msk  = (const float*)d_in[3];
    float* out = (float*)d_out;

    void* wm_ptr = nullptr;
    void* xr_ptr = nullptr;
    cudaGetSymbolAddress(&wm_ptr, g_wm);
    cudaGetSymbolAddress(&xr_ptr, g_xr);

    // prep: W*M and x converted to fp16 (same 11-bit mantissa as the tf32 path)
    int n4 = (KDIM * NDIM) / 4;
    prep_kernel<<<4096, 256>>>((const float4*)w, (const float4*)msk, (const float4*)x,
                               (uint2*)wm_ptr, (uint2*)xr_ptr, n4);

    // zero the atomic-accumulation region (tail tiles) — runs concurrent-free on stream
    zero_tail_kernel<<<TAIL_TILES, 256>>>(out);

    cudaFuncSetAttribute(gemm_kernel<64, false>,
                         cudaFuncAttributeMaxDynamicSharedMemorySize, (int)SMEM_TOTAL);
    cudaFuncSetAttribute(gemm_kernel<32, true>,
                         cudaFuncAttributeMaxDynamicSharedMemorySize, (int)SMEM_TOTAL);

    // Kernel A: 888 tiles = EXACTLY 3 waves of 296 concurrent CTAs -> no tail wave.
    gemm_kernel<64, false><<<FULL_TILES, THREADS, SMEM_TOTAL>>>(
        (const __half*)xr_ptr, (const __half*)wm_ptr, bias, out);

    // Kernel B: remaining 136 tiles, K-split x2 (272 CTAs, one half-duration wave).
    gemm_kernel<32, true><<<2 * TAIL_TILES, THREADS, SMEM_TOTAL>>>(
        (const __half*)xr_ptr, (const __half*)wm_ptr, bias, out);
}

// round 14
// speedup vs baseline: 1.0085x; 1.0085x over previous
#include <cuda_runtime.h>
#include <cuda_fp16.h>
#include <cstdint>

// ---------------- problem constants ----------------
static constexpr int MDIM = 4096;   // batch
static constexpr int NDIM = 4096;   // out features
static constexpr int KDIM = 4096;   // in features

static constexpr int BM = 128;
static constexpr int BN = 128;
static constexpr int BK = 64;                // halves per stage (128B rows)
static constexpr int THREADS = 256;          // 8 warps: 4 (m) x 2 (n), warp tile 32x64

static constexpr int TILES      = (MDIM / BM) * (NDIM / BN);  // 1024
static constexpr int FULL_TILES = 888;       // exactly 3 waves of 296 (2 CTAs x 148 SMs)
static constexpr int TAIL_TILES = TILES - FULL_TILES;         // 136 -> 272 split CTAs
static constexpr int GRID_CTAS  = FULL_TILES + 2 * TAIL_TILES;  // 1160, ONE launch

static constexpr uint32_t ASTAGE = BM * BK * 2;            // 16 KB
static constexpr uint32_t BSTAGE = BN * BK * 2;            // 16 KB
static constexpr uint32_t SLOT   = ASTAGE + BSTAGE;        // 32 KB
static constexpr uint32_t SMEM_TOTAL = 3 * SLOT;           // 96 KB -> 2 CTAs/SM

// ---------------- scratch (device globals: allocations are banned) ----------------
__device__ __align__(1024) __half g_wm[(size_t)NDIM * KDIM];  // fp16 masked weight
__device__ __align__(1024) __half g_xr[(size_t)MDIM * KDIM];  // fp16 x

// ---------------- sm_80-safe PTX helpers ----------------
__device__ __forceinline__ uint32_t smem_u32(const void* p) {
    uint32_t a;
    asm("{ .reg .u64 t; cvta.to.shared.u64 t, %1; cvt.u32.u64 %0, t; }" : "=r"(a) : "l"(p));
    return a;
}
__device__ __forceinline__ void cp_async16(uint32_t dst, const void* src) {
    asm volatile("cp.async.cg.shared.global [%0], [%1], 16;" :: "r"(dst), "l"(src) : "memory");
}
__device__ __forceinline__ void cp_commit() {
    asm volatile("cp.async.commit_group;" ::: "memory");
}
template <int N>
__device__ __forceinline__ void cp_wait() {
    asm volatile("cp.async.wait_group %0;" :: "n"(N) : "memory");
}
// Named-barrier producer/consumer split: 256 arrives + 256 syncs = 512.
__device__ __forceinline__ void bar_arrive_1() {
    asm volatile("bar.arrive 1, 512;" ::: "memory");
}
__device__ __forceinline__ void bar_sync_1() {
    asm volatile("bar.sync 1, 512;" ::: "memory");
}
__device__ __forceinline__ void ldsm_x4(uint32_t* r, uint32_t addr) {
    asm volatile("ldmatrix.sync.aligned.m8n8.x4.shared.b16 {%0,%1,%2,%3}, [%4];"
                 : "=r"(r[0]), "=r"(r[1]), "=r"(r[2]), "=r"(r[3]) : "r"(addr));
}
__device__ __forceinline__ void mma_f16(float* c, const uint32_t* a, const uint32_t* b) {
    asm volatile(
        "mma.sync.aligned.m16n8k16.row.col.f32.f16.f16.f32 "
        "{%0,%1,%2,%3}, {%4,%5,%6,%7}, {%8,%9}, {%0,%1,%2,%3};"
        : "+f"(c[0]), "+f"(c[1]), "+f"(c[2]), "+f"(c[3])
        : "r"(a[0]), "r"(a[1]), "r"(a[2]), "r"(a[3]), "r"(b[0]), "r"(b[1]));
}

// ---------------- prep: masked weight + x, both converted to fp16 RN ----------------
__global__ void prep_kernel(const float4* __restrict__ w, const float4* __restrict__ msk,
                            const float4* __restrict__ x, uint2* __restrict__ wm,
                            uint2* __restrict__ xr, int n4) {
    int stride = gridDim.x * blockDim.x;
    for (int i = blockIdx.x * blockDim.x + threadIdx.x; i < n4; i += stride) {
        float4 a = w[i], b = msk[i];
        __half2 lo = __floats2half2_rn(a.x * b.x, a.y * b.y);
        __half2 hi = __floats2half2_rn(a.z * b.z, a.w * b.w);
        uint2 o;
        o.x = *reinterpret_cast<uint32_t*>(&lo);
        o.y = *reinterpret_cast<uint32_t*>(&hi);
        wm[i] = o;
        float4 c = x[i];
        __half2 l2 = __floats2half2_rn(c.x, c.y);
        __half2 h2 = __floats2half2_rn(c.z, c.w);
        uint2 p;
        p.x = *reinterpret_cast<uint32_t*>(&l2);
        p.y = *reinterpret_cast<uint32_t*>(&h2);
        xr[i] = p;
    }
}

// ---------------- zero the tail-tile region of out (atomic accumulation base) ----------
__global__ void zero_tail_kernel(float* __restrict__ out) {
    int t  = FULL_TILES + blockIdx.x;           // tile id 888..1023
    int m0 = (t & 31) * BM;
    int n0 = (t >> 5) * BN;
    #pragma unroll
    for (int i = 0; i < 16; i++) {
        int id = threadIdx.x + 256 * i;
        int r = id >> 5, c = (id & 31) * 4;
        *reinterpret_cast<float4*>(out + (size_t)(m0 + r) * NDIM + n0 + c) =
            make_float4(0.f, 0.f, 0.f, 0.f);
    }
}

// ---------------- fp16 mma.sync GEMM: y = Xh * Wmh^T + bias (fp32 accum) ----------------
// Single launch, 1160 CTAs, in-kernel dispatch:
//   bid < 888 : full-K tile (kit=64) -> exactly 3 full waves of 296 CTAs
//   bid >= 888: tail tile K-split x2 (kit=32, kz=bid&1) -> one half-duration
//               4th wave, packed inside the SAME kernel (no inter-kernel drain,
//               which is what sank R13). Tail epilogue atomicAdds into the
//               pre-zeroed region; exactly two float contributions per address
//               onto 0.0 -> deterministic. Bias added by the kz==0 half only.
__global__ void __launch_bounds__(THREADS, 2)
gemm_kernel(const __half* __restrict__ A,   // g_xr [M][K] fp16
            const __half* __restrict__ B,   // g_wm [N][K] fp16
            const float* __restrict__ bias,
            float* __restrict__ out) {
    extern __shared__ char smem[];
    const uint32_t sbase = smem_u32(smem);
    const int tid  = threadIdx.x;
    const int lane = tid & 31;
    const int wid  = tid >> 5;
    const int wm   = wid & 3;   // warp m position (x32): 4
    const int wn   = wid >> 2;  // warp n position (x64): 2

    const int bx = (int)blockIdx.x;
    const bool split = bx >= FULL_TILES;
    int tile, kz, kit;
    if (split) {
        int t = bx - FULL_TILES;
        tile = FULL_TILES + (t >> 1);
        kz   = t & 1;
        kit  = 32;
    } else {
        tile = bx;
        kz   = 0;
        kit  = 64;
    }
    const int m0 = (tile & 31) * BM;   // m fastest -> x panels stay L2-hot
    const int n0 = (tile >> 5) * BN;
    const __half* gA = A + (size_t)m0 * KDIM + kz * (32 * BK);
    const __half* gB = B + (size_t)n0 * KDIM + kz * (32 * BK);

    // -------- stage loader: 8 x 16B cp.async per thread --------
    auto load_stage = [&](int kt, uint32_t st) {
        const int kof = kt * BK;
        #pragma unroll
        for (int i = 0; i < 4; i++) {                 // A: 1024 chunks (128 rows x 8)
            int id = tid + THREADS * i;
            int r = id >> 3, c = id & 7;
            cp_async16(st + r * 128 + ((c ^ (r & 7)) << 4),
                       gA + (size_t)r * KDIM + kof + c * 8);
        }
        #pragma unroll
        for (int i = 0; i < 4; i++) {                 // B: 1024 chunks
            int id = tid + THREADS * i;
            int r = id >> 3, c = id & 7;
            cp_async16(st + ASTAGE + r * 128 + ((c ^ (r & 7)) << 4),
                       gB + (size_t)r * KDIM + kof + c * 8);
        }
    };

    // -------- per-lane fragment base addresses (relative to stage base) --------
    uint32_t afB[2], bfB[4];
    #pragma unroll
    for (int mt = 0; mt < 2; mt++) {
        int r = wm * 32 + mt * 16 + (lane & 15);
        int b = lane >> 4, k = r & 7;
        afB[mt] = r * 128 + (((b ^ (k & 1)) | (k & 6)) << 4);
    }
    #pragma unroll
    for (int p = 0; p < 4; p++) {
        int r = wn * 64 + p * 16 + (lane & 7) + ((lane >> 4) << 3);
        int b = (lane >> 3) & 1, k = r & 7;
        bfB[p] = (ASTAGE + r * 128) + (((b ^ (k & 1)) | (k & 6)) << 4);
    }

    float acc[2][8][4];
    #pragma unroll
    for (int mt = 0; mt < 2; mt++)
        #pragma unroll
        for (int nt = 0; nt < 8; nt++)
            #pragma unroll
            for (int i = 0; i < 4; i++) acc[mt][nt][i] = 0.0f;

    // -------- prologue: stages 0,1 in flight --------
    uint32_t stC = sbase, stN = sbase + SLOT, stL = sbase + 2 * SLOT;
    load_stage(0, stC); cp_commit();
    load_stage(1, stN); cp_commit();
    cp_wait<1>();
    __syncthreads();

    // -------- main K loop --------
    for (int kt = 0; kt < kit; kt++) {
        if (kt) bar_sync_1();   // all kt-1 arrives seen: stL free, stage-kt data published
        if (kt + 2 < kit) load_stage(kt + 2, stL);
        cp_commit();  // always commit to keep group accounting uniform

        #pragma unroll
        for (int s = 0; s < 3; s++) {                 // k16 steps 0..2
            const uint32_t sx = (uint32_t)(s << 5);
            uint32_t af[2][4], bf[8][2];
            #pragma unroll
            for (int mt = 0; mt < 2; mt++)
                ldsm_x4(af[mt], stC + (afB[mt] ^ sx));
            #pragma unroll
            for (int p = 0; p < 4; p++) {
                uint32_t t[4];
                ldsm_x4(t, stC + (bfB[p] ^ sx));
                bf[2 * p][0] = t[0];     bf[2 * p][1] = t[1];
                bf[2 * p + 1][0] = t[2]; bf[2 * p + 1][1] = t[3];
            }
            #pragma unroll
            for (int mt = 0; mt < 2; mt++)
                #pragma unroll
                for (int nt = 0; nt < 8; nt++)
                    mma_f16(acc[mt][nt], af[mt], bf[nt]);
        }

        // ----- step s=3: LDSM, publish (non-blocking), then register-only MMAs -----
        {
            const uint32_t sx = 3u << 5;
            uint32_t af[2][4], bf[8][2];
            #pragma unroll
            for (int mt = 0; mt < 2; mt++)
                ldsm_x4(af[mt], stC + (afB[mt] ^ sx));
            #pragma unroll
            for (int p = 0; p < 4; p++) {
                uint32_t t[4];
                ldsm_x4(t, stC + (bfB[p] ^ sx));
                bf[2 * p][0] = t[0];     bf[2 * p][1] = t[1];
                bf[2 * p + 1][0] = t[2]; bf[2 * p + 1][1] = t[3];
            }
            cp_wait<1>();      // my stage-(kt+1) cp.async group complete
            bar_arrive_1();    // non-blocking: reads of stC done + data landed
            #pragma unroll
            for (int mt = 0; mt < 2; mt++)
                #pragma unroll
                for (int nt = 0; nt < 8; nt++)
                    mma_f16(acc[mt][nt], af[mt], bf[nt]);
        }

        uint32_t t = stC; stC = stN; stN = stL; stL = t;
    }
    cp_wait<0>();  // drain tail groups before exit

    // -------- epilogue --------
    const int r  = lane >> 2;
    const int c2 = (lane & 3) * 2;
    const float* bp = bias + n0 + wn * 64;
    float* op = out + (size_t)(m0 + wm * 32) * NDIM + n0 + wn * 64;

    #pragma unroll
    for (int mt = 0; mt < 2; mt++) {
        #pragma unroll
        for (int nt = 0; nt < 8; nt++) {
            int n = nt * 8 + c2;
            float b0, b1;
            if (split) {
                b0 = (kz == 0) ? __ldg(bp + n) : 0.0f;      // bias once (kz=0 half)
                b1 = (kz == 0) ? __ldg(bp + n + 1) : 0.0f;
            } else {
                b0 = __ldg(bp + n); b1 = __ldg(bp + n + 1);
            }
            float v00 = acc[mt][nt][0] + b0, v01 = acc[mt][nt][1] + b1;
            float v10 = acc[mt][nt][2] + b0, v11 = acc[mt][nt][3] + b1;
            float* p0 = op + (size_t)(mt * 16 + r) * NDIM + n;
            float* p1 = op + (size_t)(mt * 16 + r + 8) * NDIM + n;
            if (split) {
                atomicAdd(p0, v00); atomicAdd(p0 + 1, v01);
                atomicAdd(p1, v10); atomicAdd(p1 + 1, v11);
            } else {
                *reinterpret_cast<float2*>(p0) = make_float2(v00, v01);
                *reinterpret_cast<float2*>(p1) = make_float2(v10, v11);
            }
        }
    }
}

// ---------------- host ----------------
extern "C" void kernel_launch(void* const* d_in, const int* in_sizes, int n_in,
                              void* d_out, int out_size) {
    const float* x    = (const float*)d_in[0];
    const float* w    = (const float*)d_in[1];
    const float* bias = (const float*)d_in[2];
    const float* msk  = (const float*)d_in[3];
    float* out = (float*)d_out;

    void* wm_ptr = nullptr;
    void* xr_ptr = nullptr;
    cudaGetSymbolAddress(&wm_ptr, g_wm);
    cudaGetSymbolAddress(&xr_ptr, g_xr);

    // prep: W*M and x converted to fp16 (same 11-bit mantissa as the tf32 path)
    int n4 = (KDIM * NDIM) / 4;
    prep_kernel<<<4096, 256>>>((const float4*)w, (const float4*)msk, (const float4*)x,
                               (uint2*)wm_ptr, (uint2*)xr_ptr, n4);

    // zero the atomic-accumulation region (tail tiles)
    zero_tail_kernel<<<TAIL_TILES, 256>>>(out);

    cudaFuncSetAttribute(gemm_kernel, cudaFuncAttributeMaxDynamicSharedMemorySize,
                         (int)SMEM_TOTAL);

    // ONE launch: bids 0..887 full-K (3 exact waves), bids 888..1159 the K-split
    // tail (one half-duration 4th wave) — packed by in-order bid dispatch.
    gemm_kernel<<<GRID_CTAS, THREADS, SMEM_TOTAL>>>(
        (const __half*)xr_ptr, (const __half*)wm_ptr, bias, out);
}

// round 15
// speedup vs baseline: 1.0185x; 1.0099x over previous
#include <cuda_runtime.h>
#include <cuda_fp16.h>
#include <cstdint>

// ---------------- problem constants ----------------
static constexpr int MDIM = 4096;   // batch
static constexpr int NDIM = 4096;   // out features
static constexpr int KDIM = 4096;   // in features

static constexpr int BM = 128;
static constexpr int BN = 128;
static constexpr int BK = 64;                // halves per stage (128B rows)
static constexpr int THREADS = 256;          // 8 warps: 4 (m) x 2 (n), warp tile 32x64
static constexpr int KITERS  = KDIM / BK;    // 64

static constexpr uint32_t ASTAGE = BM * BK * 2;            // 16 KB
static constexpr uint32_t BSTAGE = BN * BK * 2;            // 16 KB
static constexpr uint32_t SLOT   = ASTAGE + BSTAGE;        // 32 KB
static constexpr uint32_t SMEM_TOTAL = 3 * SLOT;           // 96 KB -> 2 CTAs/SM

// ---------------- scratch (device globals: allocations are banned) ----------------
__device__ __align__(1024) __half g_wm[(size_t)NDIM * KDIM];  // fp16 masked weight
__device__ __align__(1024) __half g_xr[(size_t)MDIM * KDIM];  // fp16 x

// ---------------- sm_80-safe PTX helpers ----------------
__device__ __forceinline__ uint32_t smem_u32(const void* p) {
    uint32_t a;
    asm("{ .reg .u64 t; cvta.to.shared.u64 t, %1; cvt.u32.u64 %0, t; }" : "=r"(a) : "l"(p));
    return a;
}
__device__ __forceinline__ void cp_async16(uint32_t dst, const void* src) {
    asm volatile("cp.async.cg.shared.global [%0], [%1], 16;" :: "r"(dst), "l"(src) : "memory");
}
__device__ __forceinline__ void cp_commit() {
    asm volatile("cp.async.commit_group;" ::: "memory");
}
template <int N>
__device__ __forceinline__ void cp_wait() {
    asm volatile("cp.async.wait_group %0;" :: "n"(N) : "memory");
}
// Named-barrier producer/consumer split: 256 arrives + 256 syncs = 512.
__device__ __forceinline__ void bar_arrive_1() {
    asm volatile("bar.arrive 1, 512;" ::: "memory");
}
__device__ __forceinline__ void bar_sync_1() {
    asm volatile("bar.sync 1, 512;" ::: "memory");
}
__device__ __forceinline__ void ldsm_x4(uint32_t* r, uint32_t addr) {
    asm volatile("ldmatrix.sync.aligned.m8n8.x4.shared.b16 {%0,%1,%2,%3}, [%4];"
                 : "=r"(r[0]), "=r"(r[1]), "=r"(r[2]), "=r"(r[3]) : "r"(addr));
}
__device__ __forceinline__ void mma_f16(float* c, const uint32_t* a, const uint32_t* b) {
    asm volatile(
        "mma.sync.aligned.m16n8k16.row.col.f32.f16.f16.f32 "
        "{%0,%1,%2,%3}, {%4,%5,%6,%7}, {%8,%9}, {%0,%1,%2,%3};"
        : "+f"(c[0]), "+f"(c[1]), "+f"(c[2]), "+f"(c[3])
        : "r"(a[0]), "r"(a[1]), "r"(a[2]), "r"(a[3]), "r"(b[0]), "r"(b[1]));
}

// ---------------- prep: masked weight + x, both converted to fp16 RN ----------------
__global__ void prep_kernel(const float4* __restrict__ w, const float4* __restrict__ msk,
                            const float4* __restrict__ x, uint2* __restrict__ wm,
                            uint2* __restrict__ xr, int n4) {
    int stride = gridDim.x * blockDim.x;
    for (int i = blockIdx.x * blockDim.x + threadIdx.x; i < n4; i += stride) {
        float4 a = w[i], b = msk[i];
        __half2 lo = __floats2half2_rn(a.x * b.x, a.y * b.y);
        __half2 hi = __floats2half2_rn(a.z * b.z, a.w * b.w);
        uint2 o;
        o.x = *reinterpret_cast<uint32_t*>(&lo);
        o.y = *reinterpret_cast<uint32_t*>(&hi);
        wm[i] = o;
        float4 c = x[i];
        __half2 l2 = __floats2half2_rn(c.x, c.y);
        __half2 h2 = __floats2half2_rn(c.z, c.w);
        uint2 p;
        p.x = *reinterpret_cast<uint32_t*>(&l2);
        p.y = *reinterpret_cast<uint32_t*>(&h2);
        xr[i] = p;
    }
}

// ---------------- fp16 mma.sync GEMM: y = Xh * Wmh^T + bias (fp32 accum) ----------------
// R12 base (best: 296.4us GEMM) with LSU smoothing:
//  - each k16 step's LDSMs issue BEFORE that step's prefetch cp.asyncs, so the
//    loads the tensor pipe waits on never queue behind LDGSTS on the LSU;
//  - the 8 prefetch cp.asyncs are spread 2-per-step across the 4 steps
//    (commit at s=3), flattening the post-barrier LSU spike into the steady
//    state. Group accounting identical: one group per kt, cp_wait<1> at s=3
//    still publishes stage kt+1 (committed during kt-1).
__global__ void __launch_bounds__(THREADS, 2)
gemm_kernel(const __half* __restrict__ A,   // g_xr [M][K] fp16
            const __half* __restrict__ B,   // g_wm [N][K] fp16
            const float* __restrict__ bias,
            float* __restrict__ out) {
    extern __shared__ char smem[];
    const uint32_t sbase = smem_u32(smem);
    const int tid  = threadIdx.x;
    const int lane = tid & 31;
    const int wid  = tid >> 5;
    const int wm   = wid & 3;   // warp m position (x32): 4
    const int wn   = wid >> 2;  // warp n position (x64): 2

    const int m0 = blockIdx.x * BM;
    const int n0 = blockIdx.y * BN;
    const __half* gA = A + (size_t)m0 * KDIM;
    const __half* gB = B + (size_t)n0 * KDIM;

    // -------- loader quarter: 2 x 16B cp.async per thread (q = 0..3) --------
    // q0,q1 -> A halves; q2,q3 -> B halves.
    auto load_quarter = [&](int kt, uint32_t st, int q) {
        const int kof = kt * BK;
        #pragma unroll
        for (int i = 0; i < 2; i++) {
            int id = tid + THREADS * (2 * (q & 1) + i);
            int r = id >> 3, c = id & 7;
            if (q < 2) {
                cp_async16(st + r * 128 + ((c ^ (r & 7)) << 4),
                           gA + (size_t)r * KDIM + kof + c * 8);
            } else {
                cp_async16(st + ASTAGE + r * 128 + ((c ^ (r & 7)) << 4),
                           gB + (size_t)r * KDIM + kof + c * 8);
            }
        }
    };
    auto load_stage = [&](int kt, uint32_t st) {
        #pragma unroll
        for (int q = 0; q < 4; q++) load_quarter(kt, st, q);
    };

    // -------- per-lane fragment base addresses (relative to stage base) --------
    uint32_t afB[2], bfB[4];
    #pragma unroll
    for (int mt = 0; mt < 2; mt++) {
        int r = wm * 32 + mt * 16 + (lane & 15);
        int b = lane >> 4, k = r & 7;
        afB[mt] = r * 128 + (((b ^ (k & 1)) | (k & 6)) << 4);
    }
    #pragma unroll
    for (int p = 0; p < 4; p++) {
        int r = wn * 64 + p * 16 + (lane & 7) + ((lane >> 4) << 3);
        int b = (lane >> 3) & 1, k = r & 7;
        bfB[p] = (ASTAGE + r * 128) + (((b ^ (k & 1)) | (k & 6)) << 4);
    }

    float acc[2][8][4];
    #pragma unroll
    for (int mt = 0; mt < 2; mt++)
        #pragma unroll
        for (int nt = 0; nt < 8; nt++)
            #pragma unroll
            for (int i = 0; i < 4; i++) acc[mt][nt][i] = 0.0f;

    // -------- prologue: stages 0,1 in flight --------
    uint32_t stC = sbase, stN = sbase + SLOT, stL = sbase + 2 * SLOT;
    load_stage(0, stC); cp_commit();
    load_stage(1, stN); cp_commit();
    cp_wait<1>();
    __syncthreads();

    // -------- main K loop --------
    for (int kt = 0; kt < KITERS; kt++) {
        if (kt) bar_sync_1();   // all kt-1 arrives seen: stL free, stage-kt data published
        const bool pf = (kt + 2 < KITERS);

        #pragma unroll
        for (int s = 0; s < 4; s++) {                 // 4 k16 steps
            const uint32_t sx = (uint32_t)(s << 5);
            uint32_t af[2][4], bf[8][2];
            // fragments FIRST (tensor-feeding loads ahead of prefetch on LSU)
            #pragma unroll
            for (int mt = 0; mt < 2; mt++)
                ldsm_x4(af[mt], stC + (afB[mt] ^ sx));
            #pragma unroll
            for (int p = 0; p < 4; p++) {
                uint32_t t[4];
                ldsm_x4(t, stC + (bfB[p] ^ sx));
                bf[2 * p][0] = t[0];     bf[2 * p][1] = t[1];
                bf[2 * p + 1][0] = t[2]; bf[2 * p + 1][1] = t[3];
            }
            // prefetch quarter for stage kt+2 (2 cp.asyncs), spread over steps
            if (pf) load_quarter(kt + 2, stL, s);
            if (s == 3) {
                cp_commit();       // close this kt's (possibly empty) group
                cp_wait<1>();      // stage kt+1 (committed during kt-1) landed
                bar_arrive_1();    // non-blocking: stC reads done + data landed
            }
            #pragma unroll
            for (int mt = 0; mt < 2; mt++)
                #pragma unroll
                for (int nt = 0; nt < 8; nt++)
                    mma_f16(acc[mt][nt], af[mt], bf[nt]);
        }

        uint32_t t = stC; stC = stN; stN = stL; stL = t;
    }
    cp_wait<0>();  // drain tail groups before exit

    // -------- epilogue: bias add + float2 stores --------
    const int r  = lane >> 2;
    const int c2 = (lane & 3) * 2;
    const float* bp = bias + n0 + wn * 64;
    float* op = out + (size_t)(m0 + wm * 32) * NDIM + n0 + wn * 64;

    #pragma unroll
    for (int mt = 0; mt < 2; mt++) {
        #pragma unroll
        for (int nt = 0; nt < 8; nt++) {
            int n = nt * 8 + c2;
            float b0 = __ldg(bp + n), b1 = __ldg(bp + n + 1);
            float2 v0 = {acc[mt][nt][0] + b0, acc[mt][nt][1] + b1};
            float2 v1 = {acc[mt][nt][2] + b0, acc[mt][nt][3] + b1};
            *reinterpret_cast<float2*>(op + (size_t)(mt * 16 + r) * NDIM + n) = v0;
            *reinterpret_cast<float2*>(op + (size_t)(mt * 16 + r + 8) * NDIM + n) = v1;
        }
    }
}

// ---------------- host ----------------
extern "C" void kernel_launch(void* const* d_in, const int* in_sizes, int n_in,
                              void* d_out, int out_size) {
    const float* x    = (const float*)d_in[0];
    const float* w    = (const float*)d_in[1];
    const float* bias = (const float*)d_in[2];
    const float* msk  = (const float*)d_in[3];
    float* out = (float*)d_out;

    void* wm_ptr = nullptr;
    void* xr_ptr = nullptr;
    cudaGetSymbolAddress(&wm_ptr, g_wm);
    cudaGetSymbolAddress(&xr_ptr, g_xr);

    // prep: W*M and x converted to fp16 (same 11-bit mantissa as the tf32 path)
    int n4 = (KDIM * NDIM) / 4;
    prep_kernel<<<4096, 256>>>((const float4*)w, (const float4*)msk, (const float4*)x,
                               (uint2*)wm_ptr, (uint2*)xr_ptr, n4);

    cudaFuncSetAttribute(gemm_kernel, cudaFuncAttributeMaxDynamicSharedMemorySize,
                         (int)SMEM_TOTAL);

    // m fastest in blockIdx.x: backfill scheduling keeps SMs busy (R13/R14 showed
    // no wave-quantization loss); x panels stay L2-hot.
    dim3 grid(MDIM / BM, NDIM / BN, 1);  // (32, 32)
    gemm_kernel<<<grid, THREADS, SMEM_TOTAL>>>((const __half*)xr_ptr, (const __half*)wm_ptr,
                                               bias, out);
}